// round 3
// baseline (speedup 1.0000x reference)
#include <cuda_runtime.h>

// ---------------------------------------------------------------------------
// TorchFovea: foveated Laplacian-pyramid blend.
// R3: separable 1D fovea filters + mega-fused small levels (6 launches total).
// ---------------------------------------------------------------------------

#define NPL 96   // 32 batches * 3 channels

#define H0 360
#define W0 640
#define H1 180
#define W1 320
#define H2 90
#define W2 160
#define H3 45
#define W3 80
#define H4 23
#define W4 40
#define H5 12
#define W5 20

// 1D filter pyramid: row lengths 1279,640,320,160,80 ; col lengths 719,360,180,90,45
#define ROWV_TOT (1279 + 640 + 320 + 160 + 80)
#define COLV_TOT (719 + 360 + 180 + 90 + 45)
// offsets
#define RO0 0
#define RO1 1279
#define RO2 1919
#define RO3 2239
#define RO4 2399
#define CO0 0
#define CO1 719
#define CO2 1079
#define CO3 1259
#define CO4 1349

// ---- scratch ---------------------------------------------------------------
__device__ float g_rowv[ROWV_TOT];
__device__ float g_colv[COLV_TOT];
__device__ float g_dn1[NPL * H1 * W1];
__device__ float g_dn2[NPL * H2 * W2];
__device__ float g_F2[NPL * H2 * W2];
__device__ float g_F1[NPL * H1 * W1];

// reflect-101 (jnp.pad mode='reflect')
__device__ __forceinline__ int refl(int i, int n) {
    i = (i < 0) ? -i : i;
    return (i >= n) ? (2 * n - 2 - i) : i;
}

// ---------------------------------------------------------------------------
// 1D pyrdown sample: 5-tap binomial at decimated position with reflect.
// ---------------------------------------------------------------------------
__device__ __forceinline__ float pd1_at(const float* __restrict__ v, int N, int o) {
    int x = 2 * o;
    return 0.375f * v[x]
         + 0.25f  * (v[refl(x - 1, N)] + v[refl(x + 1, N)])
         + 0.0625f * (v[refl(x - 2, N)] + v[refl(x + 2, N)]);
}

// ---------------------------------------------------------------------------
// Single-block kernel: build all 5 levels of the separable fovea filter
// as 1D row/col vectors. f0(y,x) = colv0[y]*rowv0[x] exactly; pyrdown of a
// separable image is the separable product of 1D pyrdowns.
// ---------------------------------------------------------------------------
__global__ void gen_filters_kernel(float* __restrict__ rowv, float* __restrict__ colv) {
    const int t = threadIdx.x;
    const int NT = blockDim.x;
    for (int i = t; i < 1279; i += NT) {
        float d = (float)(i - 640);
        rowv[RO0 + i] = expf(-d * d / 10082.0f);
    }
    for (int j = t; j < 719; j += NT) {
        float d = (float)(j - 360);
        colv[CO0 + j] = expf(-d * d / 10082.0f);
    }
    __syncthreads();
    const int rN[5] = {1279, 640, 320, 160, 80};
    const int rO[5] = {RO0, RO1, RO2, RO3, RO4};
    const int cN[5] = {719, 360, 180, 90, 45};
    const int cO[5] = {CO0, CO1, CO2, CO3, CO4};
#pragma unroll
    for (int k = 1; k < 5; k++) {
        const float* ri = rowv + rO[k - 1];
        float* ro = rowv + rO[k];
        for (int o = t; o < rN[k]; o += NT) ro[o] = pd1_at(ri, rN[k - 1], o);
        const float* ci = colv + cO[k - 1];
        float* co = colv + cO[k];
        for (int o = t; o < cN[k]; o += NT) co[o] = pd1_at(ci, cN[k - 1], o);
        __syncthreads();
    }
}

// ---------------------------------------------------------------------------
// Tiled separable pyrDown (global->global), used for the two big levels.
// ---------------------------------------------------------------------------
#define PDX 32
#define PDY 8
__global__ void pyrdown_tiled(const float* __restrict__ src, float* __restrict__ dst,
                              int H, int W, int oH, int oW) {
    int c = blockIdx.z;
    const float* s = src + (size_t)c * H * W;
    float* d = dst + (size_t)c * oH * oW;
    int ox0 = blockIdx.x * PDX;
    int oy0 = blockIdx.y * PDY;

    __shared__ float hbuf[2 * PDY + 4][PDX];

    const float k0 = 0.0625f, k1 = 0.25f, k2 = 0.375f;
    int tid = threadIdx.y * PDX + threadIdx.x;
    const int NH = (2 * PDY + 4) * PDX;
#pragma unroll
    for (int idx = tid; idx < NH; idx += PDX * PDY) {
        int j = idx & (PDX - 1);
        int r = idx >> 5;
        int ox = ox0 + j;
        if (ox < oW) {
            int iy = refl(2 * oy0 - 2 + r, H);
            const float* row = s + (size_t)iy * W;
            int ix = 2 * ox;
            float v = k2 * row[ix]
                    + k1 * (row[refl(ix - 1, W)] + row[refl(ix + 1, W)])
                    + k0 * (row[refl(ix - 2, W)] + row[refl(ix + 2, W)]);
            hbuf[r][j] = v;
        }
    }
    __syncthreads();

    int ox = ox0 + threadIdx.x;
    int oy = oy0 + threadIdx.y;
    if (ox < oW && oy < oH) {
        int r = 2 * threadIdx.y;
        float v = k0 * (hbuf[r][threadIdx.x] + hbuf[r + 4][threadIdx.x])
                + k1 * (hbuf[r + 1][threadIdx.x] + hbuf[r + 3][threadIdx.x])
                + k2 * hbuf[r + 2][threadIdx.x];
        d[(size_t)oy * oW + ox] = v;
    }
}

// ---------------------------------------------------------------------------
// Pointwise 2D pyrdown sample from an in-smem plane.
// ---------------------------------------------------------------------------
__device__ __forceinline__ float pd2_at(const float* __restrict__ s, int H, int W,
                                        int y, int x) {
    int ry[5], rx[5];
#pragma unroll
    for (int i = 0; i < 5; i++) {
        ry[i] = refl(2 * y - 2 + i, H);
        rx[i] = refl(2 * x - 2 + i, W);
    }
    const float k0 = 0.0625f, k1 = 0.25f, k2 = 0.375f;
    float acc = 0.0f;
#pragma unroll
    for (int i = 0; i < 5; i++) {
        const float* row = s + ry[i] * W;
        float r = k2 * row[rx[2]]
                + k1 * (row[rx[1]] + row[rx[3]])
                + k0 * (row[rx[0]] + row[rx[4]]);
        float kw = (i == 2) ? k2 : ((i == 1 || i == 3) ? k1 : k0);
        acc += kw * r;
    }
    return acc;
}

// ---------------------------------------------------------------------------
// Pointwise pyrUp evaluation (reflect on the 2H x 2W grid).
// ---------------------------------------------------------------------------
__device__ __forceinline__ float pyrup_at(const float* __restrict__ s,
                                          int H, int W, int y, int x) {
    int sy[3]; float wy[3]; int ny;
    if ((y & 1) == 0) {
        sy[0] = refl(y - 2, 2 * H) >> 1; wy[0] = 0.125f;
        sy[1] = y >> 1;                  wy[1] = 0.75f;
        sy[2] = refl(y + 2, 2 * H) >> 1; wy[2] = 0.125f;
        ny = 3;
    } else {
        sy[0] = (y - 1) >> 1;            wy[0] = 0.5f;
        sy[1] = refl(y + 1, 2 * H) >> 1; wy[1] = 0.5f;
        ny = 2;
    }
    int sx[3]; float wx[3]; int nx;
    if ((x & 1) == 0) {
        sx[0] = refl(x - 2, 2 * W) >> 1; wx[0] = 0.125f;
        sx[1] = x >> 1;                  wx[1] = 0.75f;
        sx[2] = refl(x + 2, 2 * W) >> 1; wx[2] = 0.125f;
        nx = 3;
    } else {
        sx[0] = (x - 1) >> 1;            wx[0] = 0.5f;
        sx[1] = refl(x + 1, 2 * W) >> 1; wx[1] = 0.5f;
        nx = 2;
    }
    float acc = 0.0f;
#pragma unroll 3
    for (int i = 0; i < ny; i++) {
        const float* row = s + sy[i] * W;
        float r = 0.0f;
#pragma unroll 3
        for (int j = 0; j < nx; j++) r += wx[j] * row[sx[j]];
        acc += wy[i] * r;
    }
    return acc;
}

// ---------------------------------------------------------------------------
// Mega-fused small levels: one block per plane. From the dn2 plane, compute
// dn3, dn4, dn5 and reconstruct F4, F3, F2 entirely in shared memory.
// smem layout (floats): dn2 14400 | dn3 3600 | dn4 920 | dn5 240 | F4 920 | F3 3600
// ---------------------------------------------------------------------------
#define SM_DN2 0
#define SM_DN3 14400
#define SM_DN4 18000
#define SM_DN5 18920
#define SM_F4  19160
#define SM_F3  20080
#define SM_TOT 23680   // floats -> 94720 bytes

__global__ void __launch_bounds__(256) fused_small_kernel(
        const float* __restrict__ dn2,
        const float* __restrict__ colv, const float* __restrict__ rowv,
        const float* __restrict__ fixations,
        float* __restrict__ F2out) {
    extern __shared__ float sm[];
    float* s_dn2 = sm + SM_DN2;
    float* s_dn3 = sm + SM_DN3;
    float* s_dn4 = sm + SM_DN4;
    float* s_dn5 = sm + SM_DN5;
    float* s_F4  = sm + SM_F4;
    float* s_F3  = sm + SM_F3;

    const int p = blockIdx.x;
    const int b = p / 3;
    const int t = threadIdx.x;
    const int NT = 256;

    // load dn2 plane (90x160)
    const float4* src4 = (const float4*)(dn2 + (size_t)p * (H2 * W2));
    for (int i = t; i < (H2 * W2) / 4; i += NT) ((float4*)s_dn2)[i] = src4[i];
    __syncthreads();

    // dn3 = pyrdown(dn2)  (45x80)
    for (int o = t; o < H3 * W3; o += NT)
        s_dn3[o] = pd2_at(s_dn2, H2, W2, o / W3, o % W3);
    __syncthreads();
    // dn4 (23x40)
    for (int o = t; o < H4 * W4; o += NT)
        s_dn4[o] = pd2_at(s_dn3, H3, W3, o / W4, o % W4);
    __syncthreads();
    // dn5 (12x20)
    for (int o = t; o < H5 * W5; o += NT)
        s_dn5[o] = pd2_at(s_dn4, H4, W4, o / W5, o % W5);
    __syncthreads();

    const float fxx = fixations[2 * b];
    const float fyy = fixations[2 * b + 1];

    // ---- level 4: filter 45x80, out 23x40 ----
    {
        float fx = fxx * 0.0625f, fy = fyy * 0.0625f;
        int x1 = min(max((int)(40.0f - fx), 0), W3 - W4);
        int y1 = min(max((int)(22.5f - fy), 0), H3 - H4);
        const float* cv = colv + CO4 + y1;
        const float* rv = rowv + RO4 + x1;
        for (int o = t; o < H4 * W4; o += NT) {
            int y = o / W4, x = o % W4;
            float u = pyrup_at(s_dn5, H5, W5, y, x);
            float w = cv[y] * rv[x];
            s_F4[o] = u + (s_dn4[o] - u) * w;
        }
    }
    __syncthreads();

    // ---- level 3: filter 90x160, out 45x80 ----
    {
        float fx = fxx * 0.125f, fy = fyy * 0.125f;
        int x1 = min(max((int)(80.0f - fx), 0), W2 - W3);
        int y1 = min(max((int)(45.0f - fy), 0), H2 - H3);
        const float* cv = colv + CO3 + y1;
        const float* rv = rowv + RO3 + x1;
        for (int o = t; o < H3 * W3; o += NT) {
            int y = o / W3, x = o % W3;
            float uF = pyrup_at(s_F4, H4, W4, y, x);
            float uD = pyrup_at(s_dn4, H4, W4, y, x);
            float w = cv[y] * rv[x];
            s_F3[o] = uF + (s_dn3[o] - uD) * w;
        }
    }
    __syncthreads();

    // ---- level 2: filter 180x320, out 90x160 -> global ----
    {
        float fx = fxx * 0.25f, fy = fyy * 0.25f;
        int x1 = min(max((int)(160.0f - fx), 0), W1 - W2);
        int y1 = min(max((int)(90.0f - fy), 0), H1 - H2);
        const float* cv = colv + CO2 + y1;
        const float* rv = rowv + RO2 + x1;
        float* outp = F2out + (size_t)p * (H2 * W2);
        for (int o = t; o < H2 * W2; o += NT) {
            int y = o / W2, x = o % W2;
            float uF = pyrup_at(s_F3, H3, W3, y, x);
            float uD = pyrup_at(s_dn3, H3, W3, y, x);
            float w = cv[y] * rv[x];
            outp[o] = uF + (s_dn2[o] - uD) * w;
        }
    }
}

// ---------------------------------------------------------------------------
// Quad reconstruction with separable filter weights (levels 1 and 0).
// ---------------------------------------------------------------------------
__global__ void recon_quad(const float* __restrict__ Fsrc,
                           const float* __restrict__ Dnext,
                           int sH, int sW,
                           const float* __restrict__ Dcur,
                           const float* __restrict__ colv,
                           const float* __restrict__ rowv,
                           int fH, int fW,
                           const float* __restrict__ fixations,
                           float invscale,
                           float* __restrict__ out, int oH, int oW) {
    int qW = oW >> 1;
    int qH = (oH + 1) >> 1;
    int qx = blockIdx.x * blockDim.x + threadIdx.x;
    int qy = blockIdx.y * blockDim.y + threadIdx.y;
    if (qx >= qW || qy >= qH) return;
    int p = blockIdx.z;
    int b = p / 3;

    float fx = fixations[2 * b]     * invscale;
    float fy = fixations[2 * b + 1] * invscale;
    int x1 = min(max((int)((float)fW * 0.5f - fx), 0), fW - oW);
    int y1 = min(max((int)((float)fH * 0.5f - fy), 0), fH - oH);

    int xl = (qx == 0) ? 1 : qx - 1;
    int xr = refl(2 * qx + 2, 2 * sW) >> 1;
    int yu = (qy == 0) ? 1 : qy - 1;
    int yd = refl(2 * qy + 2, 2 * sH) >> 1;

    size_t soff = (size_t)p * sH * sW;
    const float* Fs = Fsrc + soff;
    const float* Dn = Dnext + soff;

    float uF_ee, uF_eo, uF_oe, uF_oo;
    float uD_ee, uD_eo, uD_oe, uD_oo;
    {
        const float* r0 = Fs + (size_t)yu * sW;
        const float* r1 = Fs + (size_t)qy * sW;
        const float* r2 = Fs + (size_t)yd * sW;
        float a00 = r0[xl], a01 = r0[qx], a02 = r0[xr];
        float a10 = r1[xl], a11 = r1[qx], a12 = r1[xr];
        float a20 = r2[xl], a21 = r2[qx], a22 = r2[xr];
        float he0 = 0.125f * (a00 + a02) + 0.75f * a01;
        float he1 = 0.125f * (a10 + a12) + 0.75f * a11;
        float he2 = 0.125f * (a20 + a22) + 0.75f * a21;
        float ho0 = 0.5f * (a01 + a02);
        float ho1 = 0.5f * (a11 + a12);
        float ho2 = 0.5f * (a21 + a22);
        uF_ee = 0.125f * (he0 + he2) + 0.75f * he1;
        uF_eo = 0.125f * (ho0 + ho2) + 0.75f * ho1;
        uF_oe = 0.5f * (he1 + he2);
        uF_oo = 0.5f * (ho1 + ho2);
    }
    {
        const float* r0 = Dn + (size_t)yu * sW;
        const float* r1 = Dn + (size_t)qy * sW;
        const float* r2 = Dn + (size_t)yd * sW;
        float a00 = r0[xl], a01 = r0[qx], a02 = r0[xr];
        float a10 = r1[xl], a11 = r1[qx], a12 = r1[xr];
        float a20 = r2[xl], a21 = r2[qx], a22 = r2[xr];
        float he0 = 0.125f * (a00 + a02) + 0.75f * a01;
        float he1 = 0.125f * (a10 + a12) + 0.75f * a11;
        float he2 = 0.125f * (a20 + a22) + 0.75f * a21;
        float ho0 = 0.5f * (a01 + a02);
        float ho1 = 0.5f * (a11 + a12);
        float ho2 = 0.5f * (a21 + a22);
        uD_ee = 0.125f * (he0 + he2) + 0.75f * he1;
        uD_eo = 0.125f * (ho0 + ho2) + 0.75f * ho1;
        uD_oe = 0.5f * (he1 + he2);
        uD_oo = 0.5f * (ho1 + ho2);
    }

    int x0 = 2 * qx;
    int y0 = 2 * qy;
    size_t obase = (size_t)p * oH * oW;
    float rw0 = rowv[x0 + x1], rw1 = rowv[x0 + 1 + x1];

    {
        float cw = colv[y0 + y1];
        const float2 dc = *(const float2*)(Dcur + obase + (size_t)y0 * oW + x0);
        float2 o;
        o.x = uF_ee + (dc.x - uD_ee) * (cw * rw0);
        o.y = uF_eo + (dc.y - uD_eo) * (cw * rw1);
        *(float2*)(out + obase + (size_t)y0 * oW + x0) = o;
    }
    if (y0 + 1 < oH) {
        float cw = colv[y0 + 1 + y1];
        const float2 dc = *(const float2*)(Dcur + obase + (size_t)(y0 + 1) * oW + x0);
        float2 o;
        o.x = uF_oe + (dc.x - uD_oe) * (cw * rw0);
        o.y = uF_oo + (dc.y - uD_oo) * (cw * rw1);
        *(float2*)(out + obase + (size_t)(y0 + 1) * oW + x0) = o;
    }
}

// ---------------------------------------------------------------------------

static inline int idiv(int a, int b) { return (a + b - 1) / b; }

extern "C" void kernel_launch(void* const* d_in, const int* in_sizes, int n_in,
                              void* d_out, int out_size) {
    (void)in_sizes; (void)n_in; (void)out_size;
    const float* images = (const float*)d_in[0];
    const float* fix    = (const float*)d_in[1];
    float* out = (float*)d_out;

    float *rowv, *colv, *dn1, *dn2, *F2, *F1;
    cudaGetSymbolAddress((void**)&rowv, g_rowv);
    cudaGetSymbolAddress((void**)&colv, g_colv);
    cudaGetSymbolAddress((void**)&dn1, g_dn1);
    cudaGetSymbolAddress((void**)&dn2, g_dn2);
    cudaGetSymbolAddress((void**)&F2, g_F2);
    cudaGetSymbolAddress((void**)&F1, g_F1);

    cudaFuncSetAttribute(fused_small_kernel,
                         cudaFuncAttributeMaxDynamicSharedMemorySize,
                         SM_TOT * (int)sizeof(float));

    // 1. separable fovea filters (all levels)
    gen_filters_kernel<<<1, 256>>>(rowv, colv);

    // 2-3. big pyrdowns
    {
        dim3 blk(PDX, PDY);
        dim3 g1(idiv(W1, PDX), idiv(H1, PDY), NPL);
        pyrdown_tiled<<<g1, blk>>>(images, dn1, H0, W0, H1, W1);
        dim3 g2(idiv(W2, PDX), idiv(H2, PDY), NPL);
        pyrdown_tiled<<<g2, blk>>>(dn1, dn2, H1, W1, H2, W2);
    }

    // 4. fused small levels: dn3..dn5 + recon 4..2 -> F2
    fused_small_kernel<<<NPL, 256, SM_TOT * (int)sizeof(float)>>>(
        dn2, colv, rowv, fix, F2);

    // 5. recon level 1 -> F1
    {
        dim3 blk(32, 8);
        dim3 grd(idiv(W1 / 2, 32), idiv((H1 + 1) / 2, 8), NPL);
        recon_quad<<<grd, blk>>>(F2, dn2, H2, W2, dn1,
                                 colv + CO1, rowv + RO1, H0, W0,
                                 fix, 0.5f, F1, H1, W1);
    }
    // 6. recon level 0 -> out
    {
        dim3 blk(32, 8);
        dim3 grd(idiv(W0 / 2, 32), idiv((H0 + 1) / 2, 8), NPL);
        recon_quad<<<grd, blk>>>(F1, dn1, H1, W1, images,
                                 colv + CO0, rowv + RO0, 719, 1279,
                                 fix, 1.0f, out, H0, W0);
    }
}

// round 4
// speedup vs baseline: 1.5749x; 1.5749x over previous
#include <cuda_runtime.h>

// ---------------------------------------------------------------------------
// TorchFovea: foveated Laplacian-pyramid blend.
// R4: separable 1D filters, 1024-thread fused mid-levels (dn3..F3),
//     quad recon for levels 2/1/0. 7 launches.
// ---------------------------------------------------------------------------

#define NPL 96

#define H0 360
#define W0 640
#define H1 180
#define W1 320
#define H2 90
#define W2 160
#define H3 45
#define W3 80
#define H4 23
#define W4 40
#define H5 12
#define W5 20

#define ROWV_TOT (1279 + 640 + 320 + 160 + 80)
#define COLV_TOT (719 + 360 + 180 + 90 + 45)
#define RO0 0
#define RO1 1279
#define RO2 1919
#define RO3 2239
#define RO4 2399
#define CO0 0
#define CO1 719
#define CO2 1079
#define CO3 1259
#define CO4 1349

// ---- scratch ---------------------------------------------------------------
__device__ float g_rowv[ROWV_TOT];
__device__ float g_colv[COLV_TOT];
__device__ float g_dn1[NPL * H1 * W1];
__device__ float g_dn2[NPL * H2 * W2];
__device__ float g_dn3[NPL * H3 * W3];
__device__ float g_F3[NPL * H3 * W3];
__device__ float g_F2[NPL * H2 * W2];
__device__ float g_F1[NPL * H1 * W1];

__device__ __forceinline__ int refl(int i, int n) {
    i = (i < 0) ? -i : i;
    return (i >= n) ? (2 * n - 2 - i) : i;
}

// ---------------------------------------------------------------------------
__device__ __forceinline__ float pd1_at(const float* __restrict__ v, int N, int o) {
    int x = 2 * o;
    return 0.375f * v[x]
         + 0.25f  * (v[refl(x - 1, N)] + v[refl(x + 1, N)])
         + 0.0625f * (v[refl(x - 2, N)] + v[refl(x + 2, N)]);
}

__global__ void gen_filters_kernel(float* __restrict__ rowv, float* __restrict__ colv) {
    const int t = threadIdx.x;
    const int NT = blockDim.x;
    for (int i = t; i < 1279; i += NT) {
        float d = (float)(i - 640);
        rowv[RO0 + i] = expf(-d * d / 10082.0f);
    }
    for (int j = t; j < 719; j += NT) {
        float d = (float)(j - 360);
        colv[CO0 + j] = expf(-d * d / 10082.0f);
    }
    __syncthreads();
    const int rN[5] = {1279, 640, 320, 160, 80};
    const int rO[5] = {RO0, RO1, RO2, RO3, RO4};
    const int cN[5] = {719, 360, 180, 90, 45};
    const int cO[5] = {CO0, CO1, CO2, CO3, CO4};
#pragma unroll
    for (int k = 1; k < 5; k++) {
        const float* ri = rowv + rO[k - 1];
        float* ro = rowv + rO[k];
        for (int o = t; o < rN[k]; o += NT) ro[o] = pd1_at(ri, rN[k - 1], o);
        const float* ci = colv + cO[k - 1];
        float* co = colv + cO[k];
        for (int o = t; o < cN[k]; o += NT) co[o] = pd1_at(ci, cN[k - 1], o);
        __syncthreads();
    }
}

// ---------------------------------------------------------------------------
// Tiled separable pyrDown (global->global), big levels only.
// ---------------------------------------------------------------------------
#define PDX 32
#define PDY 8
__global__ void pyrdown_tiled(const float* __restrict__ src, float* __restrict__ dst,
                              int H, int W, int oH, int oW) {
    int c = blockIdx.z;
    const float* s = src + (size_t)c * H * W;
    float* d = dst + (size_t)c * oH * oW;
    int ox0 = blockIdx.x * PDX;
    int oy0 = blockIdx.y * PDY;

    __shared__ float hbuf[2 * PDY + 4][PDX];

    const float k0 = 0.0625f, k1 = 0.25f, k2 = 0.375f;
    int tid = threadIdx.y * PDX + threadIdx.x;
    const int NH = (2 * PDY + 4) * PDX;
#pragma unroll
    for (int idx = tid; idx < NH; idx += PDX * PDY) {
        int j = idx & (PDX - 1);
        int r = idx >> 5;
        int ox = ox0 + j;
        if (ox < oW) {
            int iy = refl(2 * oy0 - 2 + r, H);
            const float* row = s + (size_t)iy * W;
            int ix = 2 * ox;
            float v = k2 * row[ix]
                    + k1 * (row[refl(ix - 1, W)] + row[refl(ix + 1, W)])
                    + k0 * (row[refl(ix - 2, W)] + row[refl(ix + 2, W)]);
            hbuf[r][j] = v;
        }
    }
    __syncthreads();

    int ox = ox0 + threadIdx.x;
    int oy = oy0 + threadIdx.y;
    if (ox < oW && oy < oH) {
        int r = 2 * threadIdx.y;
        float v = k0 * (hbuf[r][threadIdx.x] + hbuf[r + 4][threadIdx.x])
                + k1 * (hbuf[r + 1][threadIdx.x] + hbuf[r + 3][threadIdx.x])
                + k2 * hbuf[r + 2][threadIdx.x];
        d[(size_t)oy * oW + ox] = v;
    }
}

// ---------------------------------------------------------------------------
__device__ __forceinline__ float pd2_at(const float* __restrict__ s, int H, int W,
                                        int y, int x) {
    int ry[5], rx[5];
#pragma unroll
    for (int i = 0; i < 5; i++) {
        ry[i] = refl(2 * y - 2 + i, H);
        rx[i] = refl(2 * x - 2 + i, W);
    }
    const float k0 = 0.0625f, k1 = 0.25f, k2 = 0.375f;
    float acc = 0.0f;
#pragma unroll
    for (int i = 0; i < 5; i++) {
        const float* row = s + ry[i] * W;
        float r = k2 * row[rx[2]]
                + k1 * (row[rx[1]] + row[rx[3]])
                + k0 * (row[rx[0]] + row[rx[4]]);
        float kw = (i == 2) ? k2 : ((i == 1 || i == 3) ? k1 : k0);
        acc += kw * r;
    }
    return acc;
}

__device__ __forceinline__ float pyrup_at(const float* __restrict__ s,
                                          int H, int W, int y, int x) {
    int sy[3]; float wy[3]; int ny;
    if ((y & 1) == 0) {
        sy[0] = refl(y - 2, 2 * H) >> 1; wy[0] = 0.125f;
        sy[1] = y >> 1;                  wy[1] = 0.75f;
        sy[2] = refl(y + 2, 2 * H) >> 1; wy[2] = 0.125f;
        ny = 3;
    } else {
        sy[0] = (y - 1) >> 1;            wy[0] = 0.5f;
        sy[1] = refl(y + 1, 2 * H) >> 1; wy[1] = 0.5f;
        ny = 2;
    }
    int sx[3]; float wx[3]; int nx;
    if ((x & 1) == 0) {
        sx[0] = refl(x - 2, 2 * W) >> 1; wx[0] = 0.125f;
        sx[1] = x >> 1;                  wx[1] = 0.75f;
        sx[2] = refl(x + 2, 2 * W) >> 1; wx[2] = 0.125f;
        nx = 3;
    } else {
        sx[0] = (x - 1) >> 1;            wx[0] = 0.5f;
        sx[1] = refl(x + 1, 2 * W) >> 1; wx[1] = 0.5f;
        nx = 2;
    }
    float acc = 0.0f;
#pragma unroll 3
    for (int i = 0; i < ny; i++) {
        const float* row = s + sy[i] * W;
        float r = 0.0f;
#pragma unroll 3
        for (int j = 0; j < nx; j++) r += wx[j] * row[sx[j]];
        acc += wy[i] * r;
    }
    return acc;
}

// ---------------------------------------------------------------------------
// Fused mid-levels, 1024 threads/block, one block per plane:
//   smem: dn2 (14400, reused as F3 buffer) | dn3 3600 | dn4 920 | dn5 240 | F4 920
//   dn3 and F3 are also written to global for the level-2 quad recon.
// ---------------------------------------------------------------------------
#define FNT 1024
#define SM_DN2 0
#define SM_DN3 14400
#define SM_DN4 18000
#define SM_DN5 18920
#define SM_F4  19160
#define SM_TOT 20080   // floats = 80320 bytes

__global__ void __launch_bounds__(FNT) fused_mid_kernel(
        const float* __restrict__ dn2,
        const float* __restrict__ colv, const float* __restrict__ rowv,
        const float* __restrict__ fixations,
        float* __restrict__ dn3g, float* __restrict__ F3g) {
    extern __shared__ float sm[];
    float* s_dn2 = sm + SM_DN2;
    float* s_dn3 = sm + SM_DN3;
    float* s_dn4 = sm + SM_DN4;
    float* s_dn5 = sm + SM_DN5;
    float* s_F4  = sm + SM_F4;
    float* s_F3  = sm + SM_DN2;   // overlay: dn2 dead after dn3 stage

    const int p = blockIdx.x;
    const int b = p / 3;
    const int t = threadIdx.x;
    const int wid = t >> 5;
    const int lane = t & 31;

    // load dn2 plane (90x160) coalesced
    const float4* src4 = (const float4*)(dn2 + (size_t)p * (H2 * W2));
    for (int i = t; i < (H2 * W2) / 4; i += FNT) ((float4*)s_dn2)[i] = src4[i];
    __syncthreads();

    // dn3 (45x80): warp-per-row, lanes over columns; also write to global
    {
        float* g = dn3g + (size_t)p * (H3 * W3);
        for (int y = wid; y < H3; y += 32) {
            for (int x = lane; x < W3; x += 32) {
                float v = pd2_at(s_dn2, H2, W2, y, x);
                s_dn3[y * W3 + x] = v;
                g[y * W3 + x] = v;
            }
        }
    }
    __syncthreads();
    // dn4 (23x40)
    for (int y = wid; y < H4; y += 32)
        for (int x = lane; x < W4; x += 32)
            s_dn4[y * W4 + x] = pd2_at(s_dn3, H3, W3, y, x);
    __syncthreads();
    // dn5 (12x20)
    for (int y = wid; y < H5; y += 32)
        for (int x = lane; x < W5; x += 32)
            s_dn5[y * W5 + x] = pd2_at(s_dn4, H4, W4, y, x);
    __syncthreads();

    const float fxx = fixations[2 * b];
    const float fyy = fixations[2 * b + 1];

    // level 4: F4 = pyrup(dn5) + (dn4 - pyrup(dn5)) * w   (23x40)
    {
        int x1 = min(max((int)(40.0f - fxx * 0.0625f), 0), W3 - W4);
        int y1 = min(max((int)(22.5f - fyy * 0.0625f), 0), H3 - H4);
        const float* cv = colv + CO4 + y1;
        const float* rv = rowv + RO4 + x1;
        for (int y = wid; y < H4; y += 32) {
            float cw = cv[y];
            for (int x = lane; x < W4; x += 32) {
                float u = pyrup_at(s_dn5, H5, W5, y, x);
                s_F4[y * W4 + x] = u + (s_dn4[y * W4 + x] - u) * (cw * rv[x]);
            }
        }
    }
    __syncthreads();

    // level 3: F3 = pyrup(F4) + (dn3 - pyrup(dn4)) * w   (45x80) -> smem + global
    {
        int x1 = min(max((int)(80.0f - fxx * 0.125f), 0), W2 - W3);
        int y1 = min(max((int)(45.0f - fyy * 0.125f), 0), H2 - H3);
        const float* cv = colv + CO3 + y1;
        const float* rv = rowv + RO3 + x1;
        float* g = F3g + (size_t)p * (H3 * W3);
        for (int y = wid; y < H3; y += 32) {
            float cw = cv[y];
            for (int x = lane; x < W3; x += 32) {
                float uF = pyrup_at(s_F4, H4, W4, y, x);
                float uD = pyrup_at(s_dn4, H4, W4, y, x);
                float v = uF + (s_dn3[y * W3 + x] - uD) * (cw * rv[x]);
                g[y * W3 + x] = v;
                (void)s_F3;
            }
        }
    }
}

// ---------------------------------------------------------------------------
// Quad reconstruction, separable weights (levels 2, 1, 0).
// ---------------------------------------------------------------------------
__global__ void recon_quad(const float* __restrict__ Fsrc,
                           const float* __restrict__ Dnext,
                           int sH, int sW,
                           const float* __restrict__ Dcur,
                           const float* __restrict__ colv,
                           const float* __restrict__ rowv,
                           int fH, int fW,
                           const float* __restrict__ fixations,
                           float invscale,
                           float* __restrict__ out, int oH, int oW) {
    int qW = oW >> 1;
    int qH = (oH + 1) >> 1;
    int qx = blockIdx.x * blockDim.x + threadIdx.x;
    int qy = blockIdx.y * blockDim.y + threadIdx.y;
    if (qx >= qW || qy >= qH) return;
    int p = blockIdx.z;
    int b = p / 3;

    float fx = fixations[2 * b]     * invscale;
    float fy = fixations[2 * b + 1] * invscale;
    int x1 = min(max((int)((float)fW * 0.5f - fx), 0), fW - oW);
    int y1 = min(max((int)((float)fH * 0.5f - fy), 0), fH - oH);

    int xl = (qx == 0) ? 1 : qx - 1;
    int xr = refl(2 * qx + 2, 2 * sW) >> 1;
    int yu = (qy == 0) ? 1 : qy - 1;
    int yd = refl(2 * qy + 2, 2 * sH) >> 1;

    size_t soff = (size_t)p * sH * sW;
    const float* Fs = Fsrc + soff;
    const float* Dn = Dnext + soff;

    float uF_ee, uF_eo, uF_oe, uF_oo;
    float uD_ee, uD_eo, uD_oe, uD_oo;
    {
        const float* r0 = Fs + (size_t)yu * sW;
        const float* r1 = Fs + (size_t)qy * sW;
        const float* r2 = Fs + (size_t)yd * sW;
        float a00 = r0[xl], a01 = r0[qx], a02 = r0[xr];
        float a10 = r1[xl], a11 = r1[qx], a12 = r1[xr];
        float a20 = r2[xl], a21 = r2[qx], a22 = r2[xr];
        float he0 = 0.125f * (a00 + a02) + 0.75f * a01;
        float he1 = 0.125f * (a10 + a12) + 0.75f * a11;
        float he2 = 0.125f * (a20 + a22) + 0.75f * a21;
        float ho0 = 0.5f * (a01 + a02);
        float ho1 = 0.5f * (a11 + a12);
        float ho2 = 0.5f * (a21 + a22);
        uF_ee = 0.125f * (he0 + he2) + 0.75f * he1;
        uF_eo = 0.125f * (ho0 + ho2) + 0.75f * ho1;
        uF_oe = 0.5f * (he1 + he2);
        uF_oo = 0.5f * (ho1 + ho2);
    }
    {
        const float* r0 = Dn + (size_t)yu * sW;
        const float* r1 = Dn + (size_t)qy * sW;
        const float* r2 = Dn + (size_t)yd * sW;
        float a00 = r0[xl], a01 = r0[qx], a02 = r0[xr];
        float a10 = r1[xl], a11 = r1[qx], a12 = r1[xr];
        float a20 = r2[xl], a21 = r2[qx], a22 = r2[xr];
        float he0 = 0.125f * (a00 + a02) + 0.75f * a01;
        float he1 = 0.125f * (a10 + a12) + 0.75f * a11;
        float he2 = 0.125f * (a20 + a22) + 0.75f * a21;
        float ho0 = 0.5f * (a01 + a02);
        float ho1 = 0.5f * (a11 + a12);
        float ho2 = 0.5f * (a21 + a22);
        uD_ee = 0.125f * (he0 + he2) + 0.75f * he1;
        uD_eo = 0.125f * (ho0 + ho2) + 0.75f * ho1;
        uD_oe = 0.5f * (he1 + he2);
        uD_oo = 0.5f * (ho1 + ho2);
    }

    int x0 = 2 * qx;
    int y0 = 2 * qy;
    size_t obase = (size_t)p * oH * oW;
    float rw0 = rowv[x0 + x1], rw1 = rowv[x0 + 1 + x1];

    {
        float cw = colv[y0 + y1];
        const float2 dc = *(const float2*)(Dcur + obase + (size_t)y0 * oW + x0);
        float2 o;
        o.x = uF_ee + (dc.x - uD_ee) * (cw * rw0);
        o.y = uF_eo + (dc.y - uD_eo) * (cw * rw1);
        *(float2*)(out + obase + (size_t)y0 * oW + x0) = o;
    }
    if (y0 + 1 < oH) {
        float cw = colv[y0 + 1 + y1];
        const float2 dc = *(const float2*)(Dcur + obase + (size_t)(y0 + 1) * oW + x0);
        float2 o;
        o.x = uF_oe + (dc.x - uD_oe) * (cw * rw0);
        o.y = uF_oo + (dc.y - uD_oo) * (cw * rw1);
        *(float2*)(out + obase + (size_t)(y0 + 1) * oW + x0) = o;
    }
}

// ---------------------------------------------------------------------------

static inline int idiv(int a, int b) { return (a + b - 1) / b; }

extern "C" void kernel_launch(void* const* d_in, const int* in_sizes, int n_in,
                              void* d_out, int out_size) {
    (void)in_sizes; (void)n_in; (void)out_size;
    const float* images = (const float*)d_in[0];
    const float* fix    = (const float*)d_in[1];
    float* out = (float*)d_out;

    float *rowv, *colv, *dn1, *dn2, *dn3, *F3, *F2, *F1;
    cudaGetSymbolAddress((void**)&rowv, g_rowv);
    cudaGetSymbolAddress((void**)&colv, g_colv);
    cudaGetSymbolAddress((void**)&dn1, g_dn1);
    cudaGetSymbolAddress((void**)&dn2, g_dn2);
    cudaGetSymbolAddress((void**)&dn3, g_dn3);
    cudaGetSymbolAddress((void**)&F3, g_F3);
    cudaGetSymbolAddress((void**)&F2, g_F2);
    cudaGetSymbolAddress((void**)&F1, g_F1);

    cudaFuncSetAttribute(fused_mid_kernel,
                         cudaFuncAttributeMaxDynamicSharedMemorySize,
                         SM_TOT * (int)sizeof(float));

    // 1. separable fovea filters
    gen_filters_kernel<<<1, 1024>>>(rowv, colv);

    // 2-3. big pyrdowns
    {
        dim3 blk(PDX, PDY);
        dim3 g1(idiv(W1, PDX), idiv(H1, PDY), NPL);
        pyrdown_tiled<<<g1, blk>>>(images, dn1, H0, W0, H1, W1);
        dim3 g2(idiv(W2, PDX), idiv(H2, PDY), NPL);
        pyrdown_tiled<<<g2, blk>>>(dn1, dn2, H1, W1, H2, W2);
    }

    // 4. fused mid levels: dn3..dn5, F4, F3
    fused_mid_kernel<<<NPL, FNT, SM_TOT * (int)sizeof(float)>>>(
        dn2, colv, rowv, fix, dn3, F3);

    // 5. recon level 2 -> F2
    {
        dim3 blk(32, 8);
        dim3 grd(idiv(W2 / 2, 32), idiv((H2 + 1) / 2, 8), NPL);
        recon_quad<<<grd, blk>>>(F3, dn3, H3, W3, dn2,
                                 colv + CO2, rowv + RO2, H1, W1,
                                 fix, 0.25f, F2, H2, W2);
    }
    // 6. recon level 1 -> F1
    {
        dim3 blk(32, 8);
        dim3 grd(idiv(W1 / 2, 32), idiv((H1 + 1) / 2, 8), NPL);
        recon_quad<<<grd, blk>>>(F2, dn2, H2, W2, dn1,
                                 colv + CO1, rowv + RO1, H0, W0,
                                 fix, 0.5f, F1, H1, W1);
    }
    // 7. recon level 0 -> out
    {
        dim3 blk(32, 8);
        dim3 grd(idiv(W0 / 2, 32), idiv((H0 + 1) / 2, 8), NPL);
        recon_quad<<<grd, blk>>>(F1, dn1, H1, W1, images,
                                 colv + CO0, rowv + RO0, 719, 1279,
                                 fix, 1.0f, out, H0, W0);
    }
}

// round 5
// speedup vs baseline: 1.5752x; 1.0002x over previous
#include <cuda_runtime.h>

// ---------------------------------------------------------------------------
// TorchFovea R5: smem-staged pyrdown, smem-tiled quad recon, quadified fused
// mid-levels. 7 launches.
// ---------------------------------------------------------------------------

#define NPL 96

#define H0 360
#define W0 640
#define H1 180
#define W1 320
#define H2 90
#define W2 160
#define H3 45
#define W3 80
#define H4 23
#define W4 40
#define H5 12
#define W5 20

#define ROWV_TOT (1279 + 640 + 320 + 160 + 80)
#define COLV_TOT (719 + 360 + 180 + 90 + 45)
#define RO0 0
#define RO1 1279
#define RO2 1919
#define RO3 2239
#define RO4 2399
#define CO0 0
#define CO1 719
#define CO2 1079
#define CO3 1259
#define CO4 1349

__device__ float g_rowv[ROWV_TOT];
__device__ float g_colv[COLV_TOT];
__device__ float g_dn1[NPL * H1 * W1];
__device__ float g_dn2[NPL * H2 * W2];
__device__ float g_dn3[NPL * H3 * W3];
__device__ float g_F3[NPL * H3 * W3];
__device__ float g_F2[NPL * H2 * W2];
__device__ float g_F1[NPL * H1 * W1];

__device__ __forceinline__ int refl(int i, int n) {
    i = (i < 0) ? -i : i;
    return (i >= n) ? (2 * n - 2 - i) : i;
}

// ---------------------------------------------------------------------------
__device__ __forceinline__ float pd1_at(const float* __restrict__ v, int N, int o) {
    int x = 2 * o;
    return 0.375f * v[x]
         + 0.25f  * (v[refl(x - 1, N)] + v[refl(x + 1, N)])
         + 0.0625f * (v[refl(x - 2, N)] + v[refl(x + 2, N)]);
}

__global__ void gen_filters_kernel(float* __restrict__ rowv, float* __restrict__ colv) {
    const int t = threadIdx.x;
    const int NT = blockDim.x;
    for (int i = t; i < 1279; i += NT) {
        float d = (float)(i - 640);
        rowv[RO0 + i] = expf(-d * d / 10082.0f);
    }
    for (int j = t; j < 719; j += NT) {
        float d = (float)(j - 360);
        colv[CO0 + j] = expf(-d * d / 10082.0f);
    }
    __syncthreads();
    const int rN[5] = {1279, 640, 320, 160, 80};
    const int rO[5] = {RO0, RO1, RO2, RO3, RO4};
    const int cN[5] = {719, 360, 180, 90, 45};
    const int cO[5] = {CO0, CO1, CO2, CO3, CO4};
#pragma unroll
    for (int k = 1; k < 5; k++) {
        const float* ri = rowv + rO[k - 1];
        float* ro = rowv + rO[k];
        for (int o = t; o < rN[k]; o += NT) ro[o] = pd1_at(ri, rN[k - 1], o);
        const float* ci = colv + cO[k - 1];
        float* co = colv + cO[k];
        for (int o = t; o < cN[k]; o += NT) co[o] = pd1_at(ci, cN[k - 1], o);
        __syncthreads();
    }
}

// ---------------------------------------------------------------------------
// pyrDown with full smem staging: coalesced input tile load, then separable
// conv entirely in smem. Block (32,8) -> 32x8 output tile.
// ---------------------------------------------------------------------------
#define PDX 32
#define PDY 8
#define INW (2 * PDX + 4)   // 68
#define INH (2 * PDY + 4)   // 20

__global__ void __launch_bounds__(PDX* PDY) pyrdown_st(
        const float* __restrict__ src, float* __restrict__ dst,
        int H, int W, int oH, int oW) {
    int c = blockIdx.z;
    const float* s = src + (size_t)c * H * W;
    float* d = dst + (size_t)c * oH * oW;
    int ox0 = blockIdx.x * PDX;
    int oy0 = blockIdx.y * PDY;

    __shared__ float in[INH][INW];
    __shared__ float hb[INH][PDX];

    int tid = threadIdx.y * PDX + threadIdx.x;
    // coalesced staging with reflect
    for (int idx = tid; idx < INH * INW; idx += PDX * PDY) {
        int r = idx / INW;
        int col = idx - r * INW;
        int gy = refl(2 * oy0 - 2 + r, H);
        int gx = refl(2 * ox0 - 2 + col, W);
        in[r][col] = s[(size_t)gy * W + gx];
    }
    __syncthreads();

    const float k0 = 0.0625f, k1 = 0.25f, k2 = 0.375f;
    // horizontal pass: hb[r][j] over taps in[r][2j .. 2j+4]
    for (int idx = tid; idx < INH * PDX; idx += PDX * PDY) {
        int r = idx >> 5;
        int j = idx & 31;
        const float* row = in[r] + 2 * j;
        hb[r][j] = k0 * (row[0] + row[4]) + k1 * (row[1] + row[3]) + k2 * row[2];
    }
    __syncthreads();

    int ox = ox0 + threadIdx.x;
    int oy = oy0 + threadIdx.y;
    if (ox < oW && oy < oH) {
        int r = 2 * threadIdx.y;
        float v = k0 * (hb[r][threadIdx.x] + hb[r + 4][threadIdx.x])
                + k1 * (hb[r + 1][threadIdx.x] + hb[r + 3][threadIdx.x])
                + k2 * hb[r + 2][threadIdx.x];
        d[(size_t)oy * oW + ox] = v;
    }
}

// ---------------------------------------------------------------------------
__device__ __forceinline__ float pd2_at(const float* __restrict__ s, int H, int W,
                                        int y, int x) {
    int ry[5], rx[5];
#pragma unroll
    for (int i = 0; i < 5; i++) {
        ry[i] = refl(2 * y - 2 + i, H);
        rx[i] = refl(2 * x - 2 + i, W);
    }
    const float k0 = 0.0625f, k1 = 0.25f, k2 = 0.375f;
    float acc = 0.0f;
#pragma unroll
    for (int i = 0; i < 5; i++) {
        const float* row = s + ry[i] * W;
        float r = k2 * row[rx[2]]
                + k1 * (row[rx[1]] + row[rx[3]])
                + k0 * (row[rx[0]] + row[rx[4]]);
        float kw = (i == 2) ? k2 : ((i == 1 || i == 3) ? k1 : k0);
        acc += kw * r;
    }
    return acc;
}

// pyrup for a 2x2 output quad (y0=2qy, x0=2qx) from one 3x3 neighborhood.
__device__ __forceinline__ void pyrup_quad(const float* __restrict__ s, int H, int W,
                                           int qy, int qx,
                                           float& ee, float& eo, float& oe, float& oo) {
    int xl = (qx == 0) ? 1 : qx - 1;
    int xr = (qx < W - 1) ? qx + 1 : W - 1;
    int yu = (qy == 0) ? 1 : qy - 1;
    int yd = (qy < H - 1) ? qy + 1 : H - 1;
    const float* r0 = s + yu * W;
    const float* r1 = s + qy * W;
    const float* r2 = s + yd * W;
    float a00 = r0[xl], a01 = r0[qx], a02 = r0[xr];
    float a10 = r1[xl], a11 = r1[qx], a12 = r1[xr];
    float a20 = r2[xl], a21 = r2[qx], a22 = r2[xr];
    float he0 = 0.125f * (a00 + a02) + 0.75f * a01;
    float he1 = 0.125f * (a10 + a12) + 0.75f * a11;
    float he2 = 0.125f * (a20 + a22) + 0.75f * a21;
    float ho0 = 0.5f * (a01 + a02);
    float ho1 = 0.5f * (a11 + a12);
    float ho2 = 0.5f * (a21 + a22);
    ee = 0.125f * (he0 + he2) + 0.75f * he1;
    eo = 0.125f * (ho0 + ho2) + 0.75f * ho1;
    oe = 0.5f * (he1 + he2);
    oo = 0.5f * (ho1 + ho2);
}

// ---------------------------------------------------------------------------
// Fused mid levels (one 1024-thread block per plane):
//   dn2(smem) -> hb3 -> dn3 (sep conv) -> dn4 -> dn5 -> F4 -> F3
//   dn3 and F3 also written to global for the tiled level-2 recon.
// smem floats: dn2 14400 | hb3 7200 | dn3 3600 | dn4 920 | dn5 240 | F4 920
// ---------------------------------------------------------------------------
#define FNT 1024
#define SM_DN2 0
#define SM_HB3 14400
#define SM_DN3 21600
#define SM_DN4 25200
#define SM_DN5 26120
#define SM_F4  26360
#define SM_TOT 27280   // 109120 bytes

__global__ void __launch_bounds__(FNT) fused_mid_kernel(
        const float* __restrict__ dn2,
        const float* __restrict__ colv, const float* __restrict__ rowv,
        const float* __restrict__ fixations,
        float* __restrict__ dn3g, float* __restrict__ F3g) {
    extern __shared__ float sm[];
    float* s_dn2 = sm + SM_DN2;
    float* s_hb3 = sm + SM_HB3;
    float* s_dn3 = sm + SM_DN3;
    float* s_dn4 = sm + SM_DN4;
    float* s_dn5 = sm + SM_DN5;
    float* s_F4  = sm + SM_F4;

    const int p = blockIdx.x;
    const int b = p / 3;
    const int t = threadIdx.x;
    const float k0 = 0.0625f, k1 = 0.25f, k2 = 0.375f;

    // stage dn2 plane (coalesced float4)
    const float4* src4 = (const float4*)(dn2 + (size_t)p * (H2 * W2));
    for (int i = t; i < (H2 * W2) / 4; i += FNT) ((float4*)s_dn2)[i] = src4[i];
    __syncthreads();

    // hb3[y][ox] : horizontal 5-tap at decimated cols (90 x 80)
    for (int idx = t; idx < H2 * W3; idx += FNT) {
        int y = idx / W3;
        int ox = idx - y * W3;
        const float* row = s_dn2 + y * W2;
        int xc = 2 * ox;
        float v;
        if (ox >= 1 && ox <= W3 - 2) {
            v = k0 * (row[xc - 2] + row[xc + 2]) + k1 * (row[xc - 1] + row[xc + 1])
              + k2 * row[xc];
        } else {
            v = k2 * row[xc]
              + k1 * (row[refl(xc - 1, W2)] + row[refl(xc + 1, W2)])
              + k0 * (row[refl(xc - 2, W2)] + row[refl(xc + 2, W2)]);
        }
        s_hb3[idx] = v;
    }
    __syncthreads();

    // dn3[oy][ox] : vertical 5-tap (45 x 80), also to global
    {
        float* g = dn3g + (size_t)p * (H3 * W3);
        for (int idx = t; idx < H3 * W3; idx += FNT) {
            int oy = idx / W3;
            int ox = idx - oy * W3;
            int yc = 2 * oy;
            float v;
            if (oy >= 1 && oy <= H3 - 2) {
                v = k0 * (s_hb3[(yc - 2) * W3 + ox] + s_hb3[(yc + 2) * W3 + ox])
                  + k1 * (s_hb3[(yc - 1) * W3 + ox] + s_hb3[(yc + 1) * W3 + ox])
                  + k2 * s_hb3[yc * W3 + ox];
            } else {
                v = k2 * s_hb3[yc * W3 + ox]
                  + k1 * (s_hb3[refl(yc - 1, H2) * W3 + ox] + s_hb3[refl(yc + 1, H2) * W3 + ox])
                  + k0 * (s_hb3[refl(yc - 2, H2) * W3 + ox] + s_hb3[refl(yc + 2, H2) * W3 + ox]);
            }
            s_dn3[idx] = v;
            g[idx] = v;
        }
    }
    __syncthreads();

    // dn4 (23x40)
    for (int idx = t; idx < H4 * W4; idx += FNT)
        s_dn4[idx] = pd2_at(s_dn3, H3, W3, idx / W4, idx % W4);
    __syncthreads();
    // dn5 (12x20)
    for (int idx = t; idx < H5 * W5; idx += FNT)
        s_dn5[idx] = pd2_at(s_dn4, H4, W4, idx / W5, idx % W5);
    __syncthreads();

    const float fxx = fixations[2 * b];
    const float fyy = fixations[2 * b + 1];

    // level 4 (quads): F4 = u + (dn4 - u)*w, out 23x40, src dn5 12x20
    {
        int x1 = min(max((int)(40.0f - fxx * 0.0625f), 0), W3 - W4);
        int y1 = min(max((int)(22.5f - fyy * 0.0625f), 0), H3 - H4);
        const float* cv = colv + CO4 + y1;
        const float* rv = rowv + RO4 + x1;
        const int qH = (H4 + 1) / 2, qW = W4 / 2;   // 12, 20
        for (int idx = t; idx < qH * qW; idx += FNT) {
            int qy = idx / qW;
            int qx = idx - qy * qW;
            float ee, eo, oe, oo;
            pyrup_quad(s_dn5, H5, W5, qy, qx, ee, eo, oe, oo);
            int y0 = 2 * qy, x0 = 2 * qx;
            float rw0 = rv[x0], rw1 = rv[x0 + 1];
            float cw0 = cv[y0];
            s_F4[y0 * W4 + x0]     = ee + (s_dn4[y0 * W4 + x0]     - ee) * (cw0 * rw0);
            s_F4[y0 * W4 + x0 + 1] = eo + (s_dn4[y0 * W4 + x0 + 1] - eo) * (cw0 * rw1);
            if (y0 + 1 < H4) {
                float cw1 = cv[y0 + 1];
                s_F4[(y0 + 1) * W4 + x0]     = oe + (s_dn4[(y0 + 1) * W4 + x0]     - oe) * (cw1 * rw0);
                s_F4[(y0 + 1) * W4 + x0 + 1] = oo + (s_dn4[(y0 + 1) * W4 + x0 + 1] - oo) * (cw1 * rw1);
            }
        }
    }
    __syncthreads();

    // level 3 (quads): F3 = uF + (dn3 - uD)*w, out 45x80, src 23x40 -> global
    {
        int x1 = min(max((int)(80.0f - fxx * 0.125f), 0), W2 - W3);
        int y1 = min(max((int)(45.0f - fyy * 0.125f), 0), H2 - H3);
        const float* cv = colv + CO3 + y1;
        const float* rv = rowv + RO3 + x1;
        float* g = F3g + (size_t)p * (H3 * W3);
        const int qH = (H3 + 1) / 2, qW = W3 / 2;   // 23, 40
        for (int idx = t; idx < qH * qW; idx += FNT) {
            int qy = idx / qW;
            int qx = idx - qy * qW;
            float Fee, Feo, Foe, Foo, Dee, Deo, Doe, Doo;
            pyrup_quad(s_F4, H4, W4, qy, qx, Fee, Feo, Foe, Foo);
            pyrup_quad(s_dn4, H4, W4, qy, qx, Dee, Deo, Doe, Doo);
            int y0 = 2 * qy, x0 = 2 * qx;
            float rw0 = rv[x0], rw1 = rv[x0 + 1];
            float cw0 = cv[y0];
            float2 o0;
            o0.x = Fee + (s_dn3[y0 * W3 + x0]     - Dee) * (cw0 * rw0);
            o0.y = Feo + (s_dn3[y0 * W3 + x0 + 1] - Deo) * (cw0 * rw1);
            *(float2*)(g + y0 * W3 + x0) = o0;
            if (y0 + 1 < H3) {
                float cw1 = cv[y0 + 1];
                float2 o1;
                o1.x = Foe + (s_dn3[(y0 + 1) * W3 + x0]     - Doe) * (cw1 * rw0);
                o1.y = Foo + (s_dn3[(y0 + 1) * W3 + x0 + 1] - Doo) * (cw1 * rw1);
                *(float2*)(g + (y0 + 1) * W3 + x0) = o1;
            }
        }
    }
}

// ---------------------------------------------------------------------------
// Tiled quad reconstruction: block (32,8) of quads -> 64x16 output tile.
// Fsrc/Dnext neighborhoods staged in smem (10x34 each, clamped loads).
// ---------------------------------------------------------------------------
__global__ void __launch_bounds__(256) recon_tiled(
        const float* __restrict__ Fsrc,
        const float* __restrict__ Dnext,
        int sH, int sW,
        const float* __restrict__ Dcur,
        const float* __restrict__ colv,
        const float* __restrict__ rowv,
        int fH, int fW,
        const float* __restrict__ fixations,
        float invscale,
        float* __restrict__ out, int oH, int oW) {
    __shared__ float sF[10][36];
    __shared__ float sD[10][36];

    int p = blockIdx.z;
    int b = p / 3;
    int qx0 = blockIdx.x * 32;
    int qy0 = blockIdx.y * 8;
    int qW = oW >> 1;
    int qH = (oH + 1) >> 1;
    size_t soff = (size_t)p * sH * sW;

    int tid = threadIdx.y * 32 + threadIdx.x;
    for (int i = tid; i < 10 * 34; i += 256) {
        int r = i / 34;
        int c2 = i - r * 34;
        int gr = qy0 - 1 + r;
        gr = (gr < 0) ? -gr : gr;
        gr = min(gr, sH - 1);
        int gc = qx0 - 1 + c2;
        gc = (gc < 0) ? -gc : gc;
        gc = min(gc, sW - 1);
        size_t off = soff + (size_t)gr * sW + gc;
        sF[r][c2] = Fsrc[off];
        sD[r][c2] = Dnext[off];
    }
    __syncthreads();

    int qx = qx0 + threadIdx.x;
    int qy = qy0 + threadIdx.y;
    if (qx >= qW || qy >= qH) return;

    float fx = fixations[2 * b]     * invscale;
    float fy = fixations[2 * b + 1] * invscale;
    int x1 = min(max((int)((float)fW * 0.5f - fx), 0), fW - oW);
    int y1 = min(max((int)((float)fH * 0.5f - fy), 0), fH - oH);

    // tile-local 3x3 indices
    int txl = ((qx == 0) ? 1 : qx - 1) - (qx0 - 1);
    int txc = threadIdx.x + 1;
    int txr = ((qx < sW - 1) ? qx + 1 : sW - 1) - (qx0 - 1);
    int tyu = ((qy == 0) ? 1 : qy - 1) - (qy0 - 1);
    int tyc = threadIdx.y + 1;
    int tyd = ((qy < sH - 1) ? qy + 1 : sH - 1) - (qy0 - 1);

    float uF_ee, uF_eo, uF_oe, uF_oo, uD_ee, uD_eo, uD_oe, uD_oo;
    {
        float a00 = sF[tyu][txl], a01 = sF[tyu][txc], a02 = sF[tyu][txr];
        float a10 = sF[tyc][txl], a11 = sF[tyc][txc], a12 = sF[tyc][txr];
        float a20 = sF[tyd][txl], a21 = sF[tyd][txc], a22 = sF[tyd][txr];
        float he0 = 0.125f * (a00 + a02) + 0.75f * a01;
        float he1 = 0.125f * (a10 + a12) + 0.75f * a11;
        float he2 = 0.125f * (a20 + a22) + 0.75f * a21;
        float ho0 = 0.5f * (a01 + a02);
        float ho1 = 0.5f * (a11 + a12);
        float ho2 = 0.5f * (a21 + a22);
        uF_ee = 0.125f * (he0 + he2) + 0.75f * he1;
        uF_eo = 0.125f * (ho0 + ho2) + 0.75f * ho1;
        uF_oe = 0.5f * (he1 + he2);
        uF_oo = 0.5f * (ho1 + ho2);
    }
    {
        float a00 = sD[tyu][txl], a01 = sD[tyu][txc], a02 = sD[tyu][txr];
        float a10 = sD[tyc][txl], a11 = sD[tyc][txc], a12 = sD[tyc][txr];
        float a20 = sD[tyd][txl], a21 = sD[tyd][txc], a22 = sD[tyd][txr];
        float he0 = 0.125f * (a00 + a02) + 0.75f * a01;
        float he1 = 0.125f * (a10 + a12) + 0.75f * a11;
        float he2 = 0.125f * (a20 + a22) + 0.75f * a21;
        float ho0 = 0.5f * (a01 + a02);
        float ho1 = 0.5f * (a11 + a12);
        float ho2 = 0.5f * (a21 + a22);
        uD_ee = 0.125f * (he0 + he2) + 0.75f * he1;
        uD_eo = 0.125f * (ho0 + ho2) + 0.75f * ho1;
        uD_oe = 0.5f * (he1 + he2);
        uD_oo = 0.5f * (ho1 + ho2);
    }

    int x0 = 2 * qx;
    int y0 = 2 * qy;
    size_t obase = (size_t)p * oH * oW;
    float rw0 = rowv[x0 + x1], rw1 = rowv[x0 + 1 + x1];

    {
        float cw = colv[y0 + y1];
        const float2 dc = *(const float2*)(Dcur + obase + (size_t)y0 * oW + x0);
        float2 o;
        o.x = uF_ee + (dc.x - uD_ee) * (cw * rw0);
        o.y = uF_eo + (dc.y - uD_eo) * (cw * rw1);
        *(float2*)(out + obase + (size_t)y0 * oW + x0) = o;
    }
    if (y0 + 1 < oH) {
        float cw = colv[y0 + 1 + y1];
        const float2 dc = *(const float2*)(Dcur + obase + (size_t)(y0 + 1) * oW + x0);
        float2 o;
        o.x = uF_oe + (dc.x - uD_oe) * (cw * rw0);
        o.y = uF_oo + (dc.y - uD_oo) * (cw * rw1);
        *(float2*)(out + obase + (size_t)(y0 + 1) * oW + x0) = o;
    }
}

// ---------------------------------------------------------------------------

static inline int idiv(int a, int b) { return (a + b - 1) / b; }

extern "C" void kernel_launch(void* const* d_in, const int* in_sizes, int n_in,
                              void* d_out, int out_size) {
    (void)in_sizes; (void)n_in; (void)out_size;
    const float* images = (const float*)d_in[0];
    const float* fix    = (const float*)d_in[1];
    float* out = (float*)d_out;

    float *rowv, *colv, *dn1, *dn2, *dn3, *F3, *F2, *F1;
    cudaGetSymbolAddress((void**)&rowv, g_rowv);
    cudaGetSymbolAddress((void**)&colv, g_colv);
    cudaGetSymbolAddress((void**)&dn1, g_dn1);
    cudaGetSymbolAddress((void**)&dn2, g_dn2);
    cudaGetSymbolAddress((void**)&dn3, g_dn3);
    cudaGetSymbolAddress((void**)&F3, g_F3);
    cudaGetSymbolAddress((void**)&F2, g_F2);
    cudaGetSymbolAddress((void**)&F1, g_F1);

    cudaFuncSetAttribute(fused_mid_kernel,
                         cudaFuncAttributeMaxDynamicSharedMemorySize,
                         SM_TOT * (int)sizeof(float));

    gen_filters_kernel<<<1, 1024>>>(rowv, colv);

    {
        dim3 blk(PDX, PDY);
        dim3 g1(idiv(W1, PDX), idiv(H1, PDY), NPL);
        pyrdown_st<<<g1, blk>>>(images, dn1, H0, W0, H1, W1);
        dim3 g2(idiv(W2, PDX), idiv(H2, PDY), NPL);
        pyrdown_st<<<g2, blk>>>(dn1, dn2, H1, W1, H2, W2);
    }

    fused_mid_kernel<<<NPL, FNT, SM_TOT * (int)sizeof(float)>>>(
        dn2, colv, rowv, fix, dn3, F3);

    {
        dim3 blk(32, 8);
        dim3 g2(idiv(W2 / 2, 32), idiv(H2 / 2, 8), NPL);
        recon_tiled<<<g2, blk>>>(F3, dn3, H3, W3, dn2,
                                 colv + CO2, rowv + RO2, H1, W1,
                                 fix, 0.25f, F2, H2, W2);
        dim3 g1(idiv(W1 / 2, 32), idiv(H1 / 2, 8), NPL);
        recon_tiled<<<g1, blk>>>(F2, dn2, H2, W2, dn1,
                                 colv + CO1, rowv + RO1, H0, W0,
                                 fix, 0.5f, F1, H1, W1);
        dim3 g0(idiv(W0 / 2, 32), idiv(H0 / 2, 8), NPL);
        recon_tiled<<<g0, blk>>>(F1, dn1, H1, W1, images,
                                 colv + CO0, rowv + RO0, 719, 1279,
                                 fix, 1.0f, out, H0, W0);
    }
}

// round 6
// speedup vs baseline: 1.8638x; 1.1832x over previous
#include <cuda_runtime.h>

// ---------------------------------------------------------------------------
// TorchFovea R6: 6 launches.
//   gen_filters | pyrdown(images->dn1) | pyrdown(dn1->dn2)
//   fused_mid: dn2 -> dn3,dn4,dn5,F4,F3,F2  (all in smem, writes only F2)
//   recon_pair level1 (F2,dn2,dn1 -> F1) | recon_pair level0 (-> out)
// ---------------------------------------------------------------------------

#define NPL 96

#define H0 360
#define W0 640
#define H1 180
#define W1 320
#define H2 90
#define W2 160
#define H3 45
#define W3 80
#define H4 23
#define W4 40
#define H5 12
#define W5 20

#define ROWV_TOT (1279 + 640 + 320 + 160 + 80)
#define COLV_TOT (719 + 360 + 180 + 90 + 45)
#define RO0 0
#define RO1 1279
#define RO2 1919
#define RO3 2239
#define RO4 2399
#define CO0 0
#define CO1 719
#define CO2 1079
#define CO3 1259
#define CO4 1349

__device__ float g_rowv[ROWV_TOT];
__device__ float g_colv[COLV_TOT];
__device__ float g_dn1[NPL * H1 * W1];
__device__ float g_dn2[NPL * H2 * W2];
__device__ float g_F2[NPL * H2 * W2];
__device__ float g_F1[NPL * H1 * W1];

__device__ __forceinline__ int refl(int i, int n) {
    i = (i < 0) ? -i : i;
    return (i >= n) ? (2 * n - 2 - i) : i;
}

// ---------------------------------------------------------------------------
__device__ __forceinline__ float pd1_at(const float* __restrict__ v, int N, int o) {
    int x = 2 * o;
    return 0.375f * v[x]
         + 0.25f  * (v[refl(x - 1, N)] + v[refl(x + 1, N)])
         + 0.0625f * (v[refl(x - 2, N)] + v[refl(x + 2, N)]);
}

__global__ void gen_filters_kernel(float* __restrict__ rowv, float* __restrict__ colv) {
    const int t = threadIdx.x;
    const int NT = blockDim.x;
    for (int i = t; i < 1279; i += NT) {
        float d = (float)(i - 640);
        rowv[RO0 + i] = expf(-d * d / 10082.0f);
    }
    for (int j = t; j < 719; j += NT) {
        float d = (float)(j - 360);
        colv[CO0 + j] = expf(-d * d / 10082.0f);
    }
    __syncthreads();
    const int rN[5] = {1279, 640, 320, 160, 80};
    const int rO[5] = {RO0, RO1, RO2, RO3, RO4};
    const int cN[5] = {719, 360, 180, 90, 45};
    const int cO[5] = {CO0, CO1, CO2, CO3, CO4};
#pragma unroll
    for (int k = 1; k < 5; k++) {
        const float* ri = rowv + rO[k - 1];
        float* ro = rowv + rO[k];
        for (int o = t; o < rN[k]; o += NT) ro[o] = pd1_at(ri, rN[k - 1], o);
        const float* ci = colv + cO[k - 1];
        float* co = colv + cO[k];
        for (int o = t; o < cN[k]; o += NT) co[o] = pd1_at(ci, cN[k - 1], o);
        __syncthreads();
    }
}

// ---------------------------------------------------------------------------
// pyrDown v2: block (16,16) -> 32x16 output tile, float2 stores.
// Full input tile (36 x 68) staged coalesced, separable conv in smem.
// ---------------------------------------------------------------------------
#define PTX 32   // out tile width
#define PTY 16   // out tile height
#define PIW (2 * PTX + 4)   // 68
#define PIH (2 * PTY + 4)   // 36

__global__ void __launch_bounds__(256) pyrdown_st(
        const float* __restrict__ src, float* __restrict__ dst,
        int H, int W, int oH, int oW) {
    int c = blockIdx.z;
    const float* s = src + (size_t)c * H * W;
    float* d = dst + (size_t)c * oH * oW;
    int ox0 = blockIdx.x * PTX;
    int oy0 = blockIdx.y * PTY;

    __shared__ float in[PIH][PIW];
    __shared__ float hb[PIH][PTX];

    int tid = threadIdx.y * 16 + threadIdx.x;
    for (int idx = tid; idx < PIH * PIW; idx += 256) {
        int r = idx / PIW;
        int col = idx - r * PIW;
        int gy = refl(2 * oy0 - 2 + r, H);
        int gx = refl(2 * ox0 - 2 + col, W);
        in[r][col] = s[(size_t)gy * W + gx];
    }
    __syncthreads();

    const float k0 = 0.0625f, k1 = 0.25f, k2 = 0.375f;
    for (int idx = tid; idx < PIH * PTX; idx += 256) {
        int r = idx >> 5;
        int j = idx & 31;
        const float* row = in[r] + 2 * j;
        hb[r][j] = k0 * (row[0] + row[4]) + k1 * (row[1] + row[3]) + k2 * row[2];
    }
    __syncthreads();

    int oy = oy0 + threadIdx.y;
    int ox = ox0 + 2 * threadIdx.x;
    if (oy < oH && ox < oW) {
        int r = 2 * threadIdx.y;
        int j = 2 * threadIdx.x;
        float2 o;
        o.x = k0 * (hb[r][j] + hb[r + 4][j]) + k1 * (hb[r + 1][j] + hb[r + 3][j])
            + k2 * hb[r + 2][j];
        o.y = k0 * (hb[r][j + 1] + hb[r + 4][j + 1]) + k1 * (hb[r + 1][j + 1] + hb[r + 3][j + 1])
            + k2 * hb[r + 2][j + 1];
        *(float2*)(d + (size_t)oy * oW + ox) = o;
    }
}

// ---------------------------------------------------------------------------
__device__ __forceinline__ float pd2_at(const float* __restrict__ s, int H, int W,
                                        int y, int x) {
    int ry[5], rx[5];
#pragma unroll
    for (int i = 0; i < 5; i++) {
        ry[i] = refl(2 * y - 2 + i, H);
        rx[i] = refl(2 * x - 2 + i, W);
    }
    const float k0 = 0.0625f, k1 = 0.25f, k2 = 0.375f;
    float acc = 0.0f;
#pragma unroll
    for (int i = 0; i < 5; i++) {
        const float* row = s + ry[i] * W;
        float r = k2 * row[rx[2]]
                + k1 * (row[rx[1]] + row[rx[3]])
                + k0 * (row[rx[0]] + row[rx[4]]);
        float kw = (i == 2) ? k2 : ((i == 1 || i == 3) ? k1 : k0);
        acc += kw * r;
    }
    return acc;
}

__device__ __forceinline__ void pyrup_quad(const float* __restrict__ s, int H, int W,
                                           int qy, int qx,
                                           float& ee, float& eo, float& oe, float& oo) {
    int xl = (qx == 0) ? 1 : qx - 1;
    int xr = (qx < W - 1) ? qx + 1 : W - 1;
    int yu = (qy == 0) ? 1 : qy - 1;
    int yd = (qy < H - 1) ? qy + 1 : H - 1;
    const float* r0 = s + yu * W;
    const float* r1 = s + qy * W;
    const float* r2 = s + yd * W;
    float a00 = r0[xl], a01 = r0[qx], a02 = r0[xr];
    float a10 = r1[xl], a11 = r1[qx], a12 = r1[xr];
    float a20 = r2[xl], a21 = r2[qx], a22 = r2[xr];
    float he0 = 0.125f * (a00 + a02) + 0.75f * a01;
    float he1 = 0.125f * (a10 + a12) + 0.75f * a11;
    float he2 = 0.125f * (a20 + a22) + 0.75f * a21;
    float ho0 = 0.5f * (a01 + a02);
    float ho1 = 0.5f * (a11 + a12);
    float ho2 = 0.5f * (a21 + a22);
    ee = 0.125f * (he0 + he2) + 0.75f * he1;
    eo = 0.125f * (ho0 + ho2) + 0.75f * ho1;
    oe = 0.5f * (he1 + he2);
    oo = 0.5f * (ho1 + ho2);
}

// ---------------------------------------------------------------------------
// Fused mid levels (1024-thread block per plane): dn2 -> dn3,dn4,dn5,F4,F3,F2.
// Only F2 goes to global. smem: dn2 | hb3(/F3 overlay) | dn3 | dn4 | dn5 | F4
// ---------------------------------------------------------------------------
#define FNT 1024
#define SM_DN2 0
#define SM_HB3 14400
#define SM_DN3 21600
#define SM_DN4 25200
#define SM_DN5 26120
#define SM_F4  26360
#define SM_TOT 27280   // 109120 bytes

__global__ void __launch_bounds__(FNT) fused_mid_kernel(
        const float* __restrict__ dn2,
        const float* __restrict__ colv, const float* __restrict__ rowv,
        const float* __restrict__ fixations,
        float* __restrict__ F2g) {
    extern __shared__ float sm[];
    float* s_dn2 = sm + SM_DN2;
    float* s_hb3 = sm + SM_HB3;
    float* s_F3  = sm + SM_HB3;   // overlay (hb3 dead after dn3)
    float* s_dn3 = sm + SM_DN3;
    float* s_dn4 = sm + SM_DN4;
    float* s_dn5 = sm + SM_DN5;
    float* s_F4  = sm + SM_F4;

    const int p = blockIdx.x;
    const int b = p / 3;
    const int t = threadIdx.x;
    const float k0 = 0.0625f, k1 = 0.25f, k2 = 0.375f;

    const float4* src4 = (const float4*)(dn2 + (size_t)p * (H2 * W2));
    for (int i = t; i < (H2 * W2) / 4; i += FNT) ((float4*)s_dn2)[i] = src4[i];
    __syncthreads();

    // hb3 (90 x 80): horizontal 5-tap at decimated cols
    for (int idx = t; idx < H2 * W3; idx += FNT) {
        int y = idx / W3;
        int ox = idx - y * W3;
        const float* row = s_dn2 + y * W2;
        int xc = 2 * ox;
        float v;
        if (ox >= 1 && ox <= W3 - 2) {
            v = k0 * (row[xc - 2] + row[xc + 2]) + k1 * (row[xc - 1] + row[xc + 1])
              + k2 * row[xc];
        } else {
            v = k2 * row[xc]
              + k1 * (row[refl(xc - 1, W2)] + row[refl(xc + 1, W2)])
              + k0 * (row[refl(xc - 2, W2)] + row[refl(xc + 2, W2)]);
        }
        s_hb3[idx] = v;
    }
    __syncthreads();

    // dn3 (45 x 80): vertical 5-tap
    for (int idx = t; idx < H3 * W3; idx += FNT) {
        int oy = idx / W3;
        int ox = idx - oy * W3;
        int yc = 2 * oy;
        float v;
        if (oy >= 1 && oy <= H3 - 2) {
            v = k0 * (s_hb3[(yc - 2) * W3 + ox] + s_hb3[(yc + 2) * W3 + ox])
              + k1 * (s_hb3[(yc - 1) * W3 + ox] + s_hb3[(yc + 1) * W3 + ox])
              + k2 * s_hb3[yc * W3 + ox];
        } else {
            v = k2 * s_hb3[yc * W3 + ox]
              + k1 * (s_hb3[refl(yc - 1, H2) * W3 + ox] + s_hb3[refl(yc + 1, H2) * W3 + ox])
              + k0 * (s_hb3[refl(yc - 2, H2) * W3 + ox] + s_hb3[refl(yc + 2, H2) * W3 + ox]);
        }
        s_dn3[idx] = v;
    }
    __syncthreads();

    for (int idx = t; idx < H4 * W4; idx += FNT)
        s_dn4[idx] = pd2_at(s_dn3, H3, W3, idx / W4, idx % W4);
    __syncthreads();
    for (int idx = t; idx < H5 * W5; idx += FNT)
        s_dn5[idx] = pd2_at(s_dn4, H4, W4, idx / W5, idx % W5);
    __syncthreads();

    const float fxx = fixations[2 * b];
    const float fyy = fixations[2 * b + 1];

    // level 4: F4 (23x40)
    {
        int x1 = min(max((int)(40.0f - fxx * 0.0625f), 0), W3 - W4);
        int y1 = min(max((int)(22.5f - fyy * 0.0625f), 0), H3 - H4);
        const float* cv = colv + CO4 + y1;
        const float* rv = rowv + RO4 + x1;
        const int qH = (H4 + 1) / 2, qW = W4 / 2;
        for (int idx = t; idx < qH * qW; idx += FNT) {
            int qy = idx / qW;
            int qx = idx - qy * qW;
            float ee, eo, oe, oo;
            pyrup_quad(s_dn5, H5, W5, qy, qx, ee, eo, oe, oo);
            int y0 = 2 * qy, x0 = 2 * qx;
            float rw0 = rv[x0], rw1 = rv[x0 + 1];
            float cw0 = cv[y0];
            s_F4[y0 * W4 + x0]     = ee + (s_dn4[y0 * W4 + x0]     - ee) * (cw0 * rw0);
            s_F4[y0 * W4 + x0 + 1] = eo + (s_dn4[y0 * W4 + x0 + 1] - eo) * (cw0 * rw1);
            if (y0 + 1 < H4) {
                float cw1 = cv[y0 + 1];
                s_F4[(y0 + 1) * W4 + x0]     = oe + (s_dn4[(y0 + 1) * W4 + x0]     - oe) * (cw1 * rw0);
                s_F4[(y0 + 1) * W4 + x0 + 1] = oo + (s_dn4[(y0 + 1) * W4 + x0 + 1] - oo) * (cw1 * rw1);
            }
        }
    }
    __syncthreads();

    // level 3: F3 (45x80) into smem (overlay of hb3)
    {
        int x1 = min(max((int)(80.0f - fxx * 0.125f), 0), W2 - W3);
        int y1 = min(max((int)(45.0f - fyy * 0.125f), 0), H2 - H3);
        const float* cv = colv + CO3 + y1;
        const float* rv = rowv + RO3 + x1;
        const int qH = (H3 + 1) / 2, qW = W3 / 2;
        for (int idx = t; idx < qH * qW; idx += FNT) {
            int qy = idx / qW;
            int qx = idx - qy * qW;
            float Fee, Feo, Foe, Foo, Dee, Deo, Doe, Doo;
            pyrup_quad(s_F4, H4, W4, qy, qx, Fee, Feo, Foe, Foo);
            pyrup_quad(s_dn4, H4, W4, qy, qx, Dee, Deo, Doe, Doo);
            int y0 = 2 * qy, x0 = 2 * qx;
            float rw0 = rv[x0], rw1 = rv[x0 + 1];
            float cw0 = cv[y0];
            s_F3[y0 * W3 + x0]     = Fee + (s_dn3[y0 * W3 + x0]     - Dee) * (cw0 * rw0);
            s_F3[y0 * W3 + x0 + 1] = Feo + (s_dn3[y0 * W3 + x0 + 1] - Deo) * (cw0 * rw1);
            if (y0 + 1 < H3) {
                float cw1 = cv[y0 + 1];
                s_F3[(y0 + 1) * W3 + x0]     = Foe + (s_dn3[(y0 + 1) * W3 + x0]     - Doe) * (cw1 * rw0);
                s_F3[(y0 + 1) * W3 + x0 + 1] = Foo + (s_dn3[(y0 + 1) * W3 + x0 + 1] - Doo) * (cw1 * rw1);
            }
        }
    }
    __syncthreads();

    // level 2: F2 (90x160) -> global (dn2 is Dcur, still resident)
    {
        int x1 = min(max((int)(160.0f - fxx * 0.25f), 0), W1 - W2);
        int y1 = min(max((int)(90.0f - fyy * 0.25f), 0), H1 - H2);
        const float* cv = colv + CO2 + y1;
        const float* rv = rowv + RO2 + x1;
        float* g = F2g + (size_t)p * (H2 * W2);
        const int qH = H2 / 2, qW = W2 / 2;   // 45, 80 (H2 even -> no guard)
        for (int idx = t; idx < qH * qW; idx += FNT) {
            int qy = idx / qW;
            int qx = idx - qy * qW;
            float Fee, Feo, Foe, Foo, Dee, Deo, Doe, Doo;
            pyrup_quad(s_F3, H3, W3, qy, qx, Fee, Feo, Foe, Foo);
            pyrup_quad(s_dn3, H3, W3, qy, qx, Dee, Deo, Doe, Doo);
            int y0 = 2 * qy, x0 = 2 * qx;
            float rw0 = rv[x0], rw1 = rv[x0 + 1];
            float cw0 = cv[y0], cw1 = cv[y0 + 1];
            float2 o0, o1;
            o0.x = Fee + (s_dn2[y0 * W2 + x0]     - Dee) * (cw0 * rw0);
            o0.y = Feo + (s_dn2[y0 * W2 + x0 + 1] - Deo) * (cw0 * rw1);
            o1.x = Foe + (s_dn2[(y0 + 1) * W2 + x0]     - Doe) * (cw1 * rw0);
            o1.y = Foo + (s_dn2[(y0 + 1) * W2 + x0 + 1] - Doo) * (cw1 * rw1);
            *(float2*)(g + y0 * W2 + x0) = o0;
            *(float2*)(g + (y0 + 1) * W2 + x0) = o1;
        }
    }
}

// ---------------------------------------------------------------------------
// recon_pair: each thread computes TWO adjacent quads = a 4x2 output block
// (float4 rows). Block (16,16) -> 64x32 output tile. Requires oW%64==0,
// qW%32==0 (true for levels 1 and 0). oH even.
// ---------------------------------------------------------------------------
#define RQX 32   // quads per tile (x)
#define RQY 16   // quads per tile (y)

__global__ void __launch_bounds__(256) recon_pair(
        const float* __restrict__ Fsrc,
        const float* __restrict__ Dnext,
        int sH, int sW,
        const float* __restrict__ Dcur,
        const float* __restrict__ colv,
        const float* __restrict__ rowv,
        int fH, int fW,
        const float* __restrict__ fixations,
        float invscale,
        float* __restrict__ out, int oH, int oW) {
    __shared__ float sF[RQY + 2][RQX + 2];
    __shared__ float sD[RQY + 2][RQX + 2];

    const int p = blockIdx.z;
    const int b = p / 3;
    const int qx0 = blockIdx.x * RQX;
    const int qy0 = blockIdx.y * RQY;
    const size_t soff = (size_t)p * sH * sW;

    int tid = threadIdx.y * 16 + threadIdx.x;
    for (int i = tid; i < (RQY + 2) * (RQX + 2); i += 256) {
        int r = i / (RQX + 2);
        int c2 = i - r * (RQX + 2);
        int gr = qy0 - 1 + r;
        gr = (gr < 0) ? -gr : gr;
        gr = min(gr, sH - 1);
        int gc = qx0 - 1 + c2;
        gc = (gc < 0) ? -gc : gc;
        gc = min(gc, sW - 1);
        size_t off = soff + (size_t)gr * sW + gc;
        sF[r][c2] = Fsrc[off];
        sD[r][c2] = Dnext[off];
    }
    __syncthreads();

    const int ty = threadIdx.y;
    const int qy = qy0 + ty;
    if (qy >= sH) return;                 // qH == sH for these levels
    const int qxA = qx0 + 2 * threadIdx.x;

    float fx = fixations[2 * b]     * invscale;
    float fy = fixations[2 * b + 1] * invscale;
    int x1 = min(max((int)((float)fW * 0.5f - fx), 0), fW - oW);
    int y1 = min(max((int)((float)fH * 0.5f - fy), 0), fH - oH);

    // tile-local indices
    const int cb = 2 * threadIdx.x + 1;                    // center of quad A
    const int la = (qxA == 0) ? 2 : cb - 1;
    const int rb = (qxA + 1 < sW - 1) ? cb + 2 : ((sW - 1) - (qx0 - 1));
    const int rc = ty + 1;
    const int ru = (qy == 0) ? 2 : ty;
    const int rd = (qy < sH - 1) ? ty + 2 : ty + 1;

    // per-array horizontal combos for rows ru, rc, rd
    float FheA[3], FhoA[3], FheB[3], FhoB[3];
    float DheA[3], DhoA[3], DheB[3], DhoB[3];
    int rows[3] = {ru, rc, rd};
#pragma unroll
    for (int i = 0; i < 3; i++) {
        int r = rows[i];
        {
            float vl = sF[r][la], v0 = sF[r][cb], v1 = sF[r][cb + 1], vr = sF[r][rb];
            FheA[i] = 0.125f * (vl + v1) + 0.75f * v0;
            FhoA[i] = 0.5f * (v0 + v1);
            FheB[i] = 0.125f * (v0 + vr) + 0.75f * v1;
            FhoB[i] = 0.5f * (v1 + vr);
        }
        {
            float vl = sD[r][la], v0 = sD[r][cb], v1 = sD[r][cb + 1], vr = sD[r][rb];
            DheA[i] = 0.125f * (vl + v1) + 0.75f * v0;
            DhoA[i] = 0.5f * (v0 + v1);
            DheB[i] = 0.125f * (v0 + vr) + 0.75f * v1;
            DhoB[i] = 0.5f * (v1 + vr);
        }
    }

    const int x0 = 2 * qxA;
    const int y0 = 2 * qy;
    const size_t obase = (size_t)p * oH * oW;
    const float* rv = rowv + x1 + x0;
    float rw0 = rv[0], rw1 = rv[1], rw2 = rv[2], rw3 = rv[3];
    float cw0 = colv[y0 + y1], cw1 = colv[y0 + 1 + y1];

    // even output row
    {
        float uF0 = 0.125f * (FheA[0] + FheA[2]) + 0.75f * FheA[1];
        float uF1 = 0.125f * (FhoA[0] + FhoA[2]) + 0.75f * FhoA[1];
        float uF2 = 0.125f * (FheB[0] + FheB[2]) + 0.75f * FheB[1];
        float uF3 = 0.125f * (FhoB[0] + FhoB[2]) + 0.75f * FhoB[1];
        float uD0 = 0.125f * (DheA[0] + DheA[2]) + 0.75f * DheA[1];
        float uD1 = 0.125f * (DhoA[0] + DhoA[2]) + 0.75f * DhoA[1];
        float uD2 = 0.125f * (DheB[0] + DheB[2]) + 0.75f * DheB[1];
        float uD3 = 0.125f * (DhoB[0] + DhoB[2]) + 0.75f * DhoB[1];
        const float4 dc = *(const float4*)(Dcur + obase + (size_t)y0 * oW + x0);
        float4 o;
        o.x = uF0 + (dc.x - uD0) * (cw0 * rw0);
        o.y = uF1 + (dc.y - uD1) * (cw0 * rw1);
        o.z = uF2 + (dc.z - uD2) * (cw0 * rw2);
        o.w = uF3 + (dc.w - uD3) * (cw0 * rw3);
        *(float4*)(out + obase + (size_t)y0 * oW + x0) = o;
    }
    // odd output row
    {
        float uF0 = 0.5f * (FheA[1] + FheA[2]);
        float uF1 = 0.5f * (FhoA[1] + FhoA[2]);
        float uF2 = 0.5f * (FheB[1] + FheB[2]);
        float uF3 = 0.5f * (FhoB[1] + FhoB[2]);
        float uD0 = 0.5f * (DheA[1] + DheA[2]);
        float uD1 = 0.5f * (DhoA[1] + DhoA[2]);
        float uD2 = 0.5f * (DheB[1] + DheB[2]);
        float uD3 = 0.5f * (DhoB[1] + DhoB[2]);
        const float4 dc = *(const float4*)(Dcur + obase + (size_t)(y0 + 1) * oW + x0);
        float4 o;
        o.x = uF0 + (dc.x - uD0) * (cw1 * rw0);
        o.y = uF1 + (dc.y - uD1) * (cw1 * rw1);
        o.z = uF2 + (dc.z - uD2) * (cw1 * rw2);
        o.w = uF3 + (dc.w - uD3) * (cw1 * rw3);
        *(float4*)(out + obase + (size_t)(y0 + 1) * oW + x0) = o;
    }
}

// ---------------------------------------------------------------------------

static inline int idiv(int a, int b) { return (a + b - 1) / b; }

extern "C" void kernel_launch(void* const* d_in, const int* in_sizes, int n_in,
                              void* d_out, int out_size) {
    (void)in_sizes; (void)n_in; (void)out_size;
    const float* images = (const float*)d_in[0];
    const float* fix    = (const float*)d_in[1];
    float* out = (float*)d_out;

    float *rowv, *colv, *dn1, *dn2, *F2, *F1;
    cudaGetSymbolAddress((void**)&rowv, g_rowv);
    cudaGetSymbolAddress((void**)&colv, g_colv);
    cudaGetSymbolAddress((void**)&dn1, g_dn1);
    cudaGetSymbolAddress((void**)&dn2, g_dn2);
    cudaGetSymbolAddress((void**)&F2, g_F2);
    cudaGetSymbolAddress((void**)&F1, g_F1);

    cudaFuncSetAttribute(fused_mid_kernel,
                         cudaFuncAttributeMaxDynamicSharedMemorySize,
                         SM_TOT * (int)sizeof(float));

    gen_filters_kernel<<<1, 1024>>>(rowv, colv);

    {
        dim3 blk(16, 16);
        dim3 g1(W1 / PTX, idiv(H1, PTY), NPL);   // (10, 12, 96)
        pyrdown_st<<<g1, blk>>>(images, dn1, H0, W0, H1, W1);
        dim3 g2(W2 / PTX, idiv(H2, PTY), NPL);   // (5, 6, 96)
        pyrdown_st<<<g2, blk>>>(dn1, dn2, H1, W1, H2, W2);
    }

    fused_mid_kernel<<<NPL, FNT, SM_TOT * (int)sizeof(float)>>>(
        dn2, colv, rowv, fix, F2);

    {
        dim3 blk(16, 16);
        dim3 g1((W1 / 2) / RQX, idiv(H1 / 2, RQY), NPL);   // (5, 6, 96)
        recon_pair<<<g1, blk>>>(F2, dn2, H2, W2, dn1,
                                colv + CO1, rowv + RO1, H0, W0,
                                fix, 0.5f, F1, H1, W1);
        dim3 g0((W0 / 2) / RQX, idiv(H0 / 2, RQY), NPL);   // (10, 12, 96)
        recon_pair<<<g0, blk>>>(F1, dn1, H1, W1, images,
                                colv + CO0, rowv + RO0, 719, 1279,
                                fix, 1.0f, out, H0, W0);
    }
}